// round 1
// baseline (speedup 1.0000x reference)
#include <cuda_runtime.h>
#include <cuda_bf16.h>
#include <cstdint>

// Problem constants
#define BATCH 16
#define CDIM 256          // embedding dim (channels)
#define HW 4096           // 64*64 pixels per image
#define NPIX 65536        // BATCH * HW
#define KCODES 1024
#define TILE_N 128        // pixels per CTA
#define TILE_K 128        // codes per k-tile
#define DCH 64            // d-chunk for codebook staging
#define NTILES 512        // NPIX / TILE_N

#define QOFF 0
#define LOSS_OFF 16777216        // 16*256*64*64
#define IDX_OFF  16777217

// scratch (no cudaMalloc allowed)
__device__ int    g_idx[NPIX];
__device__ float  g_s2[KCODES];
__device__ double g_partial[NTILES];

// ---------------------------------------------------------------------------
// Kernel 0: ||e||^2 per code
// ---------------------------------------------------------------------------
__global__ void k_s2(const float* __restrict__ cb, float* __restrict__ s2) {
    int k = blockIdx.x * blockDim.x + threadIdx.x;
    if (k < KCODES) {
        const float* row = cb + (size_t)k * CDIM;
        float s = 0.f;
        #pragma unroll 8
        for (int d = 0; d < CDIM; ++d) s += row[d] * row[d];
        s2[k] = s;
    }
}

// ---------------------------------------------------------------------------
// Kernel 1: distances GEMM + argmin.  256 threads, 1 CTA/SM.
// smem: xs[256][128] (128KB) + bs[64][128] (32KB) + s1[128]
// ---------------------------------------------------------------------------
__global__ void __launch_bounds__(256, 1)
k_argmin(const float* __restrict__ in, const float* __restrict__ cb,
         const float* __restrict__ s2g, int* __restrict__ gidx) {
    extern __shared__ float sm[];
    float* xs = sm;                       // 256*128 floats
    float* bs = sm + 256 * 128;           // 64*128 floats
    float* s1 = sm + 256 * 128 + 64 * 128;// 128 floats

    const int tid = threadIdx.x;
    const int blk = blockIdx.x;
    const int b   = blk >> 5;             // 32 tiles per image
    const int hw0 = (blk & 31) << 7;
    const float* inb = in + ((size_t)b << 20); // b * 256 * 4096

    // stage x tile: xs[d][p], coalesced float4 loads
    for (int t = tid; t < 256 * 32; t += 256) {
        int d  = t >> 5;
        int p4 = t & 31;
        float4 v = *(const float4*)(inb + (size_t)d * HW + hw0 + p4 * 4);
        *(float4*)(xs + d * TILE_N + p4 * 4) = v;
    }
    __syncthreads();

    // s1[p] = sum_d x^2 (sequential fp32)
    if (tid < TILE_N) {
        float s = 0.f;
        #pragma unroll 8
        for (int d = 0; d < CDIM; ++d) {
            float v = xs[d * TILE_N + tid];
            s += v * v;
        }
        s1[tid] = s;
    }
    __syncthreads();

    const int ty = tid >> 4;   // 0..15  (pixel groups)
    const int tx = tid & 15;   // 0..15  (code groups)

    float bestd[8];
    int   besti[8];
    float s1r[8];
    #pragma unroll
    for (int i = 0; i < 8; ++i) {
        bestd[i] = 3.4e38f;
        besti[i] = 0;
        int p = (i < 4) ? (ty * 4 + i) : (64 + ty * 4 + (i - 4));
        s1r[i] = s1[p];
    }

    for (int kt = 0; kt < KCODES / TILE_K; ++kt) {
        float mm[8][8];
        #pragma unroll
        for (int i = 0; i < 8; ++i)
            #pragma unroll
            for (int j = 0; j < 8; ++j) mm[i][j] = 0.f;

        for (int dc = 0; dc < CDIM / DCH; ++dc) {
            // stage bs[d_local][k_local] (transpose from row-major codebook)
            for (int t = tid; t < TILE_K * (DCH / 4); t += 256) {
                int kl = t & 127;
                int dq = t >> 7;   // 0..15, 4 d's each
                float4 v = *(const float4*)(cb + (size_t)(kt * TILE_K + kl) * CDIM
                                               + dc * DCH + dq * 4);
                bs[(dq * 4 + 0) * TILE_K + kl] = v.x;
                bs[(dq * 4 + 1) * TILE_K + kl] = v.y;
                bs[(dq * 4 + 2) * TILE_K + kl] = v.z;
                bs[(dq * 4 + 3) * TILE_K + kl] = v.w;
            }
            __syncthreads();

            const float* xbase = xs + (dc * DCH) * TILE_N;
            #pragma unroll 2
            for (int dl = 0; dl < DCH; ++dl) {
                const float* xr = xbase + dl * TILE_N;
                const float* br = bs + dl * TILE_K;
                float4 A0 = *(const float4*)(xr + (ty << 2));
                float4 A1 = *(const float4*)(xr + 64 + (ty << 2));
                float4 B0 = *(const float4*)(br + (tx << 2));
                float4 B1 = *(const float4*)(br + 64 + (tx << 2));
                float a[8]  = {A0.x, A0.y, A0.z, A0.w, A1.x, A1.y, A1.z, A1.w};
                float bb[8] = {B0.x, B0.y, B0.z, B0.w, B1.x, B1.y, B1.z, B1.w};
                #pragma unroll
                for (int i = 0; i < 8; ++i)
                    #pragma unroll
                    for (int j = 0; j < 8; ++j)
                        mm[i][j] = fmaf(a[i], bb[j], mm[i][j]);
            }
            __syncthreads();
        }

        // fold into distances; ascending code index within thread -> strict <
        // preserves first-occurrence tie-break.
        #pragma unroll
        for (int j = 0; j < 8; ++j) {
            int k = kt * TILE_K + ((j < 4) ? (tx * 4 + j) : (64 + tx * 4 + (j - 4)));
            float s2k = __ldg(&s2g[k]);
            #pragma unroll
            for (int i = 0; i < 8; ++i) {
                // matches ref rounding: fl( fl(s1+s2) - 2*mm ), 2*mm exact
                float dist = (s1r[i] + s2k) - 2.0f * mm[i][j];
                if (dist < bestd[i]) { bestd[i] = dist; besti[i] = k; }
            }
        }
    }

    // cross-thread (tx) reduction, lexicographic (dist, idx) min == jnp.argmin
    __syncthreads();
    float* rd = bs;                       // 128*16 floats
    int*   ri = (int*)(bs + TILE_N * 16); // 128*16 ints
    #pragma unroll
    for (int i = 0; i < 8; ++i) {
        int p = (i < 4) ? (ty * 4 + i) : (64 + ty * 4 + (i - 4));
        rd[p * 16 + tx] = bestd[i];
        ri[p * 16 + tx] = besti[i];
    }
    __syncthreads();
    if (tid < TILE_N) {
        float bd = rd[tid * 16];
        int   bi = ri[tid * 16];
        #pragma unroll
        for (int t = 1; t < 16; ++t) {
            float d = rd[tid * 16 + t];
            int   ii = ri[tid * 16 + t];
            if (d < bd || (d == bd && ii < bi)) { bd = d; bi = ii; }
        }
        gidx[(b << 12) + hw0 + tid] = bi;
    }
}

// ---------------------------------------------------------------------------
// Kernel 2: gather quantized output (coalesced writes), indices-as-float,
//           per-CTA loss partial in double.
// ---------------------------------------------------------------------------
__global__ void __launch_bounds__(256)
k_out(const float* __restrict__ in, const float* __restrict__ cb,
      const int* __restrict__ gidx, float* __restrict__ out,
      double* __restrict__ partial) {
    __shared__ int idxs[TILE_N];
    __shared__ double red[256];
    const int tid = threadIdx.x;
    const int blk = blockIdx.x;
    const int b   = blk >> 5;
    const int hw0 = (blk & 31) << 7;

    if (tid < TILE_N) {
        int v = gidx[(b << 12) + hw0 + tid];
        idxs[tid] = v;
        out[IDX_OFF + (b << 12) + hw0 + tid] = (float)v; // exact for idx<2^24
    }
    __syncthreads();

    const float* inb  = in  + ((size_t)b << 20);
    float*       outb = out + QOFF + ((size_t)b << 20);

    double acc = 0.0;
    // thread keeps fixed pixel p, walks d (good L1 reuse of its code row)
    for (int t = tid; t < CDIM * TILE_N; t += 256) {
        int d = t >> 7;
        int p = t & 127;
        float q = cb[(size_t)idxs[p] * CDIM + d];
        float x = inb[(size_t)d * HW + hw0 + p];
        outb[(size_t)d * HW + hw0 + p] = q;   // coalesced (p contiguous)
        float df = q - x;
        acc += (double)df * (double)df;
    }

    red[tid] = acc;
    __syncthreads();
    #pragma unroll
    for (int s = 128; s > 0; s >>= 1) {
        if (tid < s) red[tid] += red[tid + s];
        __syncthreads();
    }
    if (tid == 0) partial[blk] = red[0];
}

// ---------------------------------------------------------------------------
// Kernel 3: deterministic final loss reduction
// ---------------------------------------------------------------------------
__global__ void k_final(const double* __restrict__ partial, float* __restrict__ out) {
    __shared__ double red[256];
    int tid = threadIdx.x;
    double a = 0.0;
    for (int t = tid; t < NTILES; t += 256) a += partial[t];
    red[tid] = a;
    __syncthreads();
    #pragma unroll
    for (int s = 128; s > 0; s >>= 1) {
        if (tid < s) red[tid] += red[tid + s];
        __syncthreads();
    }
    if (tid == 0) {
        double mse = red[0] / (double)(NPIX * (double)CDIM);
        out[LOSS_OFF] = (float)(1.25 * mse);  // q_loss + 0.25 * e_loss
    }
}

// ---------------------------------------------------------------------------
extern "C" void kernel_launch(void* const* d_in, const int* in_sizes, int n_in,
                              void* d_out, int out_size) {
    (void)in_sizes; (void)n_in; (void)out_size;
    const float* in  = (const float*)d_in[0];
    const float* cb  = (const float*)d_in[1];
    float* out = (float*)d_out;

    int*    idx_p;
    float*  s2_p;
    double* part_p;
    cudaGetSymbolAddress((void**)&idx_p,  g_idx);
    cudaGetSymbolAddress((void**)&s2_p,   g_s2);
    cudaGetSymbolAddress((void**)&part_p, g_partial);

    const int smem1 = (256 * 128 + 64 * 128 + 128) * sizeof(float); // 164352
    cudaFuncSetAttribute(k_argmin, cudaFuncAttributeMaxDynamicSharedMemorySize, smem1);

    k_s2<<<(KCODES + 255) / 256, 256>>>(cb, s2_p);
    k_argmin<<<NTILES, 256, smem1>>>(in, cb, s2_p, idx_p);
    k_out<<<NTILES, 256>>>(in, cb, idx_p, out, part_p);
    k_final<<<1, 256>>>(part_p, out);
}